// round 17
// baseline (speedup 1.0000x reference)
#include <cuda_runtime.h>

// HierarchyInvertClassifier: out[b,k,h,w] = bias[k] + sum_{c in group k} w[c]*in[b,c,h,w]
// B=8, C=64, H=W=512, K=12. Groups are contiguous channel ranges (static).
//
// HBM-bound pure stream: 512 MiB read + 96 MiB write, zero reuse.
// R17 = R13 (ILP=4, TPB=32, 4096 blocks, ascending channel order; wall
// 94.7us, DRAM 84.5%) + SMALL-GROUP PHASE FUSION: the tiny groups
// (nodata 1, water 3, snow 2, moss 3, cloud 2 = 17% of reads) ran as
// shallow load-batch phases (4-12 outstanding LDGs vs ~40 in big groups).
// Fuse them into two multi-accumulator phases — [ch0-3: nodata+water] and
// [ch57-63: snow+moss+cloud] — keeping channel order strictly ascending
// (R15 showed scattered order costs 2.6pt DRAM).
// Phases: {0:[0..0],1:[1..3]} | {2:[4..13]} | {3} | {4} | {5} | {6} | {7} |
//         {8:[52..56]} | {9:[57..58],10:[59..61],11:[62..63]}

#define HW    (512 * 512)
#define HW4   (HW / 4)        // 65536 float4 per plane
#define CCH   64
#define KOUT  12
#define TPB   32              // threads per block (one warp)
#define ILP   4
#define VPB   (ILP * TPB)     // vec positions per block = 128
#define BLKPI (HW4 / VPB)     // blocks per image = 512

__global__ __launch_bounds__(TPB)
void hier_invert_kernel(const float4* __restrict__ in4,
                        const float*  __restrict__ w,
                        const float*  __restrict__ bias,
                        float4* __restrict__ out4)
{
    __shared__ float sw[CCH];
    __shared__ float sb[KOUT];
    int t = threadIdx.x;
    sw[t]       = w[t];
    sw[t + 32]  = w[t + 32];
    if (t < KOUT) sb[t] = bias[t];
    __syncwarp();

    int bimg = blockIdx.x >> 9;               // image index (0..7), 512 blocks/image
    int blk  = blockIdx.x & (BLKPI - 1);      // block within image
    int p0   = blk * VPB + t;                 // positions p0 + j*TPB, j=0..3

    const float4* ip = in4 + ((long)bimg * CCH) * HW4 + p0;
    float4*       op = out4 + ((long)bimg * KOUT) * HW4 + p0;

    // ---- accumulate one channel c into acc[0..3] of its group ----
#define ACCUM_CH(c, A0, A1, A2, A3) do {                                  \
        const float4* _p = ip + (long)(c) * HW4;                          \
        float4 _v0 = __ldcs(_p);                                          \
        float4 _v1 = __ldcs(_p + TPB);                                    \
        float4 _v2 = __ldcs(_p + 2 * TPB);                                \
        float4 _v3 = __ldcs(_p + 3 * TPB);                                \
        float  _wc = sw[c];                                               \
        A0.x = fmaf(_wc, _v0.x, A0.x); A0.y = fmaf(_wc, _v0.y, A0.y);     \
        A0.z = fmaf(_wc, _v0.z, A0.z); A0.w = fmaf(_wc, _v0.w, A0.w);     \
        A1.x = fmaf(_wc, _v1.x, A1.x); A1.y = fmaf(_wc, _v1.y, A1.y);     \
        A1.z = fmaf(_wc, _v1.z, A1.z); A1.w = fmaf(_wc, _v1.w, A1.w);     \
        A2.x = fmaf(_wc, _v2.x, A2.x); A2.y = fmaf(_wc, _v2.y, A2.y);     \
        A2.z = fmaf(_wc, _v2.z, A2.z); A2.w = fmaf(_wc, _v2.w, A2.w);     \
        A3.x = fmaf(_wc, _v3.x, A3.x); A3.y = fmaf(_wc, _v3.y, A3.y);     \
        A3.z = fmaf(_wc, _v3.z, A3.z); A3.w = fmaf(_wc, _v3.w, A3.w);     \
    } while (0)

#define STORE_K(k, A0, A1, A2, A3) do {                                   \
        float4* _q = op + (long)(k) * HW4;                                \
        __stcs(_q,           A0);                                         \
        __stcs(_q + TPB,     A1);                                         \
        __stcs(_q + 2 * TPB, A2);                                         \
        __stcs(_q + 3 * TPB, A3);                                         \
    } while (0)

#define INIT_ACC(k, A0, A1, A2, A3) do {                                  \
        float _b = sb[k];                                                 \
        A0 = make_float4(_b, _b, _b, _b); A1 = A0; A2 = A0; A3 = A0;      \
    } while (0)

    // ---- Phase 1 (fused): nodata [0] + water [1..3] — 4 channels, 2 acc sets
    {
        float4 n0, n1, n2, n3, w0, w1, w2, w3;
        INIT_ACC(0, n0, n1, n2, n3);
        INIT_ACC(1, w0, w1, w2, w3);
        ACCUM_CH(0, n0, n1, n2, n3);
        ACCUM_CH(1, w0, w1, w2, w3);
        ACCUM_CH(2, w0, w1, w2, w3);
        ACCUM_CH(3, w0, w1, w2, w3);
        STORE_K(0, n0, n1, n2, n3);
        STORE_K(1, w0, w1, w2, w3);
    }

    // ---- Phases 2-8: big groups, one at a time (R13 structure) ----
    {
        const int gs[7]  = {10, 6, 8, 10, 8, 6, 5};  // forest..wetland
        const int gc0[7] = {4, 14, 20, 28, 38, 46, 52};
        #pragma unroll
        for (int g = 0; g < 7; g++) {
            const int k  = g + 2;
            const int c0 = gc0[g];
            const int c1 = c0 + gs[g];
            float4 a0, a1, a2, a3;
            INIT_ACC(k, a0, a1, a2, a3);
            #pragma unroll
            for (int c = c0; c < c1; c++)
                ACCUM_CH(c, a0, a1, a2, a3);
            STORE_K(k, a0, a1, a2, a3);
        }
    }

    // ---- Phase 9 (fused): snow [57..58] + moss [59..61] + cloud [62..63]
    {
        float4 s0, s1, s2, s3, m0, m1, m2, m3, c0_, c1_, c2_, c3_;
        INIT_ACC(9,  s0, s1, s2, s3);
        INIT_ACC(10, m0, m1, m2, m3);
        INIT_ACC(11, c0_, c1_, c2_, c3_);
        ACCUM_CH(57, s0, s1, s2, s3);
        ACCUM_CH(58, s0, s1, s2, s3);
        ACCUM_CH(59, m0, m1, m2, m3);
        ACCUM_CH(60, m0, m1, m2, m3);
        ACCUM_CH(61, m0, m1, m2, m3);
        ACCUM_CH(62, c0_, c1_, c2_, c3_);
        ACCUM_CH(63, c0_, c1_, c2_, c3_);
        STORE_K(9,  s0, s1, s2, s3);
        STORE_K(10, m0, m1, m2, m3);
        STORE_K(11, c0_, c1_, c2_, c3_);
    }

#undef ACCUM_CH
#undef STORE_K
#undef INIT_ACC
}

extern "C" void kernel_launch(void* const* d_in, const int* in_sizes, int n_in,
                              void* d_out, int out_size)
{
    const float* pred_lr = (const float*)d_in[0];   // [8,64,512,512]
    const float* weights = (const float*)d_in[1];   // [64]
    const float* biases  = (const float*)d_in[2];   // [12]
    float* out = (float*)d_out;                     // [8,12,512,512]

    int blocks = 8 * BLKPI;                         // 4096

    hier_invert_kernel<<<blocks, TPB>>>(
        (const float4*)pred_lr, weights, biases, (float4*)out);
}